// round 16
// baseline (speedup 1.0000x reference)
#include <cuda_runtime.h>
#include <cuda_fp16.h>
#include <math.h>
#include <stdint.h>

// Problem constants
#define NE 12
#define NT 4096
#define NH 2048
#define NF 1280

// Shared GEMM geometry: K-chunk 64, SMEM rows 64 fp16 + 8 pad = 144B
#define CH 64
#define ROWB 144
#define APL (64 * ROWB)               // 9216  B: 64-row plane
#define BPL (128 * ROWB)              // 18432 B: 128-row plane
// ffn1: CTA 64x128, warps 2x4 (tile 32x32)
#define STG1 (APL + 2 * BPL)          // 46080: A(64), B1(128), B3(128)
#define SMEM1 (1024 + 2 * STG1)       // 93184 -> 2 CTAs/SM, 2-stage
// ffn2: CTA 128x128, warps 4x2 (tile 32x64)
#define STG2 (2 * BPL)                // 36864: A(128), B(128)
#define SMEM2 (2 * STG2)              // 73728 -> 2 CTAs/SM, 2-stage

// Scratch (static __device__ globals — allocation-free per harness rules)
// g_cnt is zero at module load; block 0 of k_sum (last kernel in the graph)
// re-zeroes it so every graph replay's k_prep starts from a clean state.
__device__ int     g_cnt[NE];
__device__ int     g_tok[NE * NT];
__device__ uint8_t g_which[NE * NT];
__device__ float   g_wgt[NE * NT];
__device__ __align__(16) uint16_t g_w1f[(size_t)NE * NF * NH];   // fp16 weights
__device__ __align__(16) uint16_t g_w3f[(size_t)NE * NF * NH];
__device__ __align__(16) uint16_t g_w2f[(size_t)NE * NH * NF];
__device__ __align__(16) uint16_t g_xf[(size_t)NT * NH];         // fp16 x
__device__ __align__(16) uint16_t g_hf[(size_t)NE * NT * NF];    // fp16 h
__device__ __align__(16) float    g_part[2][(size_t)NT * NH];    // per-choice partials

// ---------------------------------------------------------------------------
// helpers
// ---------------------------------------------------------------------------
__device__ __forceinline__ uint32_t s2u(const void* p) {
    uint32_t a;
    asm("{ .reg .u64 t; cvta.to.shared.u64 t, %1; cvt.u32.u64 %0, t; }"
        : "=r"(a) : "l"(p));
    return a;
}

__device__ __forceinline__ void ldm4(uint32_t r[4], uint32_t a) {
    asm volatile("ldmatrix.sync.aligned.m8n8.x4.shared.b16 {%0,%1,%2,%3}, [%4];"
                 : "=r"(r[0]), "=r"(r[1]), "=r"(r[2]), "=r"(r[3]) : "r"(a));
}

__device__ __forceinline__ void mmaf16(float c[4], const uint32_t a[4],
                                       uint32_t b0, uint32_t b1) {
    asm volatile(
        "mma.sync.aligned.m16n8k16.row.col.f32.f16.f16.f32 "
        "{%0,%1,%2,%3},{%4,%5,%6,%7},{%8,%9},{%0,%1,%2,%3};"
        : "+f"(c[0]), "+f"(c[1]), "+f"(c[2]), "+f"(c[3])
        : "r"(a[0]), "r"(a[1]), "r"(a[2]), "r"(a[3]), "r"(b0), "r"(b1));
}

__device__ __forceinline__ void cpa16(uint32_t dst, const void* src) {
    asm volatile("cp.async.cg.shared.global [%0], [%1], 16;" :: "r"(dst), "l"(src));
}
#define CP_COMMIT() asm volatile("cp.async.commit_group;" ::: "memory")
#define CP_WAIT(n)  asm volatile("cp.async.wait_group %0;" :: "n"(n) : "memory")

// ---------------------------------------------------------------------------
// k_prep (route + weight split fused) / k_sum
// ---------------------------------------------------------------------------
#define NW4 (NE * NF * NH / 4)         // 7,864,320 float4s per weight tensor
#define ROUTE_BLOCKS (NT / 8)          // 512 blocks x 8 warps = 1 warp/token
// Split path: each block owns 1024 float4s; each thread converts 4 at stride
// 256 (MLP=4 per thread, coalescing preserved). NW4 % 1024 == 0, so every
// block lies entirely inside one tensor -> no per-iteration tensor branch.
#define SPLIT_BLOCKS ((3 * NW4) / 1024)

__global__ void k_prep(const float4* __restrict__ w1,
                       const float4* __restrict__ w3,
                       const float4* __restrict__ w2,
                       const float*  __restrict__ x,
                       const float*  __restrict__ gw) {
    if (blockIdx.x < ROUTE_BLOCKS) {
        int wid = threadIdx.x >> 5, lane = threadIdx.x & 31;
        int tok = blockIdx.x * 8 + wid;
        const float* xr = x + (size_t)tok * NH;
        uint16_t* xo = g_xf + (size_t)tok * NH;
        float acc[NE];
#pragma unroll
        for (int e = 0; e < NE; e++) acc[e] = 0.f;
        for (int i = lane; i < NH; i += 32) {
            float xv = xr[i];
            __half hv = __float2half_rn(xv);
            xo[i] = *(uint16_t*)&hv;
#pragma unroll
            for (int e = 0; e < NE; e++) acc[e] = fmaf(xv, gw[e * NH + i], acc[e]);
        }
#pragma unroll
        for (int e = 0; e < NE; e++) {
#pragma unroll
            for (int o = 16; o > 0; o >>= 1)
                acc[e] += __shfl_xor_sync(0xffffffffu, acc[e], o);
        }
        if (lane == 0) {
            int i1 = 0;
#pragma unroll
            for (int e = 1; e < NE; e++) if (acc[e] > acc[i1]) i1 = e;
            int i2 = (i1 == 0) ? 1 : 0;
#pragma unroll
            for (int e = 0; e < NE; e++) if (e != i1 && acc[e] > acc[i2]) i2 = e;
            float wA = 1.f / (1.f + expf(acc[i2] - acc[i1]));
            float wB = 1.f - wA;
            int p1 = atomicAdd(&g_cnt[i1], 1);
            g_tok[i1 * NT + p1] = tok; g_wgt[i1 * NT + p1] = wA; g_which[i1 * NT + p1] = 0;
            int p2 = atomicAdd(&g_cnt[i2], 1);
            g_tok[i2 * NT + p2] = tok; g_wgt[i2 * NT + p2] = wB; g_which[i2 * NT + p2] = 1;
        }
        return;
    }
    // Weight split: MLP=4 per thread.
    long long base = (long long)(blockIdx.x - ROUTE_BLOCKS) * 1024 + threadIdx.x;
    const float4* s; uint2* d; long long j0;
    if (base < NW4)            { s = w1; d = (uint2*)g_w1f; j0 = base; }
    else if (base < 2LL * NW4) { s = w3; d = (uint2*)g_w3f; j0 = base - NW4; }
    else                       { s = w2; d = (uint2*)g_w2f; j0 = base - 2LL * NW4; }
    float4 v[4];
#pragma unroll
    for (int k = 0; k < 4; k++) v[k] = s[j0 + k * 256];
#pragma unroll
    for (int k = 0; k < 4; k++) {
        __half2 a = __floats2half2_rn(v[k].x, v[k].y);
        __half2 b = __floats2half2_rn(v[k].z, v[k].w);
        uint2 o; o.x = *(uint32_t*)&a; o.y = *(uint32_t*)&b;
        d[j0 + k * 256] = o;
    }
}

// out = part0 + part1; block 0 also resets g_cnt for the next graph replay.
__global__ void k_sum(float4* __restrict__ out, int n4) {
    int i = blockIdx.x * blockDim.x + threadIdx.x;
    if (blockIdx.x == 0 && threadIdx.x < NE) g_cnt[threadIdx.x] = 0;
    if (i < n4) {
        float4 a = ((const float4*)g_part[0])[i];
        float4 b = ((const float4*)g_part[1])[i];
        out[i] = make_float4(a.x + b.x, a.y + b.y, a.z + b.z, a.w + b.w);
    }
}

// ---------------------------------------------------------------------------
// k_ffn1: fused x@w1^T, x@w3^T (fp16) + SwiGLU -> fp16 h.  (R13/R15 exact)
// CTA 64x128, warps 2x4 (tile 32x32), K-chunk 64, 2-stage cp.async.
// ---------------------------------------------------------------------------
__global__ __launch_bounds__(256, 2) void k_ffn1() {
    int e = blockIdx.z;
    int cnt = g_cnt[e];
    int m0 = blockIdx.y * 64;
    if (m0 >= cnt) return;
    int n0 = blockIdx.x * 128;

    extern __shared__ char sm[];
    int* stok = (int*)sm;
    uint32_t su = s2u(sm);
    int tid = threadIdx.x, lane = tid & 31, wid = tid >> 5;
    int wM = wid >> 2, wN = wid & 3;

    if (tid < 64) {
        int r = m0 + tid;
        if (r >= cnt) r = cnt - 1;
        stok[tid] = g_tok[e * NT + r];
    }
    __syncthreads();

    const size_t wb = ((size_t)e * NF + n0) * NH;

    int ach = tid & 7, ar0 = tid >> 3;
    int bpl = tid & 1, bch = (tid >> 1) & 7, br0 = tid >> 4;
    const uint16_t* bsrc = (bpl ? g_w3f : g_w1f);
    const uint16_t* apt0 = g_xf + (size_t)stok[ar0] * NH + ach * 8;
    const uint16_t* apt1 = g_xf + (size_t)stok[ar0 + 32] * NH + ach * 8;
    const uint16_t* bpt  = bsrc + wb + (size_t)br0 * NH + bch * 8;
    uint32_t adst0 = (uint32_t)(ar0 * ROWB + ach * 16);
    uint32_t bdst0 = (uint32_t)(APL + bpl * BPL + br0 * ROWB + bch * 16);

    float C1[2][4][4], C3[2][4][4];
#pragma unroll
    for (int i = 0; i < 2; i++)
#pragma unroll
        for (int j = 0; j < 4; j++)
#pragma unroll
            for (int q = 0; q < 4; q++) { C1[i][j][q] = 0.f; C3[i][j][q] = 0.f; }

    auto issue = [&](int c, uint32_t sb) {
        int k0 = c * CH;
        cpa16(sb + adst0,             apt0 + k0);
        cpa16(sb + adst0 + 32 * ROWB, apt1 + k0);
#pragma unroll
        for (int j = 0; j < 8; j++)
            cpa16(sb + bdst0 + 16 * j * ROWB, bpt + k0 + (size_t)(16 * j) * NH);
        CP_COMMIT();
    };

    auto compute = [&](uint32_t sb) {
#pragma unroll
        for (int kk = 0; kk < 4; kk++) {
            uint32_t ao = sb + (wM * 32 + (lane & 15)) * ROWB + (lane >> 4) * 16 + kk * 32;
            uint32_t bo = sb + APL + (wN * 32 + (lane & 15)) * ROWB + (lane >> 4) * 16 + kk * 32;
            uint32_t ah[2][4], b1[2][4], b3[2][4];
#pragma unroll
            for (int mf = 0; mf < 2; mf++)
                ldm4(ah[mf], ao + mf * 16 * ROWB);
#pragma unroll
            for (int g = 0; g < 2; g++) {
                ldm4(b1[g], bo + g * 16 * ROWB);
                ldm4(b3[g], bo + BPL + g * 16 * ROWB);
            }
#pragma unroll
            for (int mf = 0; mf < 2; mf++)
#pragma unroll
                for (int nf = 0; nf < 4; nf++) {
                    int g = nf >> 1, o = nf & 1;
                    mmaf16(C1[mf][nf], ah[mf], b1[g][o], b1[g][o + 2]);
                }
#pragma unroll
            for (int mf = 0; mf < 2; mf++)
#pragma unroll
                for (int nf = 0; nf < 4; nf++) {
                    int g = nf >> 1, o = nf & 1;
                    mmaf16(C3[mf][nf], ah[mf], b3[g][o], b3[g][o + 2]);
                }
        }
    };

    constexpr int NC = NH / CH;   // 32 (even)
    issue(0, su + 1024);

#pragma unroll 1
    for (int c = 0; c < NC; c += 2) {
        CP_WAIT(0);
        __syncthreads();
        if (c + 1 < NC) issue(c + 1, su + 1024 + STG1);
        compute(su + 1024);
        CP_WAIT(0);
        __syncthreads();
        if (c + 2 < NC) issue(c + 2, su + 1024);
        compute(su + 1024 + STG1);
    }

    // Epilogue: h = silu(c1)*c3*wgt -> fp16
#pragma unroll
    for (int mf = 0; mf < 2; mf++)
#pragma unroll
        for (int nf = 0; nf < 4; nf++) {
            int rb = m0 + wM * 32 + mf * 16 + (lane >> 2);
            int cc = n0 + wN * 32 + nf * 8 + (lane & 3) * 2;
#pragma unroll
            for (int hf = 0; hf < 2; hf++) {
                int r = rb + hf * 8;
                if (r < cnt) {
                    float wg = g_wgt[e * NT + r];
                    float a0 = C1[mf][nf][hf * 2], a1 = C1[mf][nf][hf * 2 + 1];
                    float h0 = a0 / (1.f + expf(-a0)) * C3[mf][nf][hf * 2] * wg;
                    float h1 = a1 / (1.f + expf(-a1)) * C3[mf][nf][hf * 2 + 1] * wg;
                    size_t off = (size_t)(e * NT + r) * NF + cc;
                    __half2 hv = __floats2half2_rn(h0, h1);
                    *(uint32_t*)(g_hf + off) = *(uint32_t*)&hv;
                }
            }
        }
}

// ---------------------------------------------------------------------------
// k_ffn2: partial[which][tok] = h @ w2^T slice.  (R13/R15 exact)
// CTA 128x128, 8 warps 4Mx2N (warp tile 32x64). 2-stage, 2 CTAs/SM.
// ---------------------------------------------------------------------------
__global__ __launch_bounds__(256, 2) void k_ffn2() {
    int e = blockIdx.z;
    int cnt = g_cnt[e];
    int m0 = blockIdx.y * 128;
    if (m0 >= cnt) return;
    int n0 = blockIdx.x * 128;

    extern __shared__ char sm[];
    uint32_t su = s2u(sm);
    int tid = threadIdx.x, lane = tid & 31, wid = tid >> 5;
    int wM = wid >> 1, wN = wid & 1;

    const size_t wb = ((size_t)e * NH + n0) * NF;
    const size_t hb = (size_t)e * NT * NF;

    int ach = tid & 7, ar0 = tid >> 3;                  // A rows ar0+32j, j<4
    int bch = tid & 7, br0 = tid >> 3;                  // B rows br0+32j, j<4
    const uint16_t* apt[4];
#pragma unroll
    for (int j = 0; j < 4; j++) {
        int r = m0 + ar0 + 32 * j;
        if (r >= cnt) r = cnt - 1;
        apt[j] = g_hf + hb + (size_t)r * NF + ach * 8;
    }
    const uint16_t* bpt = g_w2f + wb + (size_t)br0 * NF + bch * 8;
    uint32_t adst0 = (uint32_t)(ar0 * ROWB + ach * 16);
    uint32_t bdst0 = (uint32_t)(BPL + br0 * ROWB + bch * 16);

    float C[2][8][4];
#pragma unroll
    for (int i = 0; i < 2; i++)
#pragma unroll
        for (int j = 0; j < 8; j++)
#pragma unroll
            for (int q = 0; q < 4; q++) C[i][j][q] = 0.f;

    auto issue = [&](int c, uint32_t sb) {
        int k0 = c * CH;
#pragma unroll
        for (int j = 0; j < 4; j++)
            cpa16(sb + adst0 + 32 * j * ROWB, apt[j] + k0);
#pragma unroll
        for (int j = 0; j < 4; j++)
            cpa16(sb + bdst0 + 32 * j * ROWB, bpt + k0 + (size_t)(32 * j) * NF);
        CP_COMMIT();
    };

    auto compute = [&](uint32_t sb) {
#pragma unroll
        for (int kk = 0; kk < 4; kk++) {
            uint32_t ao = sb + (wM * 32 + (lane & 15)) * ROWB + (lane >> 4) * 16 + kk * 32;
            uint32_t bo = sb + BPL + (wN * 64 + (lane & 15)) * ROWB + (lane >> 4) * 16 + kk * 32;
            uint32_t ah[2][4], b[4][4];
#pragma unroll
            for (int mf = 0; mf < 2; mf++)
                ldm4(ah[mf], ao + mf * 16 * ROWB);
#pragma unroll
            for (int g = 0; g < 4; g++)
                ldm4(b[g], bo + g * 16 * ROWB);
#pragma unroll
            for (int mf = 0; mf < 2; mf++)
#pragma unroll
                for (int nf = 0; nf < 8; nf++) {
                    int g = nf >> 1, o = nf & 1;
                    mmaf16(C[mf][nf], ah[mf], b[g][o], b[g][o + 2]);
                }
        }
    };

    constexpr int NC = NF / CH;   // 20 (even)
    issue(0, su);

#pragma unroll 1
    for (int c = 0; c < NC; c += 2) {
        CP_WAIT(0);
        __syncthreads();
        if (c + 1 < NC) issue(c + 1, su + STG2);
        compute(su);
        CP_WAIT(0);
        __syncthreads();
        if (c + 2 < NC) issue(c + 2, su);
        compute(su + STG2);
    }

    // Epilogue: direct store to partial plane (each (tok,which) written once)
#pragma unroll
    for (int mf = 0; mf < 2; mf++)
#pragma unroll
        for (int nf = 0; nf < 8; nf++) {
            int rb = m0 + wM * 32 + mf * 16 + (lane >> 2);
            int cc = n0 + wN * 64 + nf * 8 + (lane & 3) * 2;
#pragma unroll
            for (int hf = 0; hf < 2; hf++) {
                int r = rb + hf * 8;
                if (r < cnt) {
                    int tok = g_tok[e * NT + r];
                    int wh  = g_which[e * NT + r];
                    float* p = g_part[wh] + (size_t)tok * NH + cc;
                    p[0] = C[mf][nf][hf * 2 + 0];
                    p[1] = C[mf][nf][hf * 2 + 1];
                }
            }
        }
}

// ---------------------------------------------------------------------------
// kernel_launch: prep (route+split) -> ffn1 -> ffn2 -> sum (sum resets g_cnt)
// ---------------------------------------------------------------------------
extern "C" void kernel_launch(void* const* d_in, const int* in_sizes, int n_in,
                              void* d_out, int out_size) {
    const float* x  = (const float*)d_in[0];
    const float* gw = (const float*)d_in[1];
    const float* w1 = (const float*)d_in[2];
    const float* w2 = (const float*)d_in[3];
    const float* w3 = (const float*)d_in[4];
    float* out = (float*)d_out;
    (void)in_sizes; (void)n_in;

    static bool attr_set = false;
    if (!attr_set) {
        cudaFuncSetAttribute(k_ffn1, cudaFuncAttributeMaxDynamicSharedMemorySize, SMEM1);
        cudaFuncSetAttribute(k_ffn2, cudaFuncAttributeMaxDynamicSharedMemorySize, SMEM2);
        attr_set = true;
    }

    k_prep<<<ROUTE_BLOCKS + SPLIT_BLOCKS, 256>>>(
        (const float4*)w1, (const float4*)w3, (const float4*)w2, x, gw);

    dim3 g1(NF / 128, NT / 64, NE);    // (10, 64, 12)
    k_ffn1<<<g1, 256, SMEM1>>>();

    dim3 g2(NH / 128, NT / 128, NE);   // (16, 32, 12)
    k_ffn2<<<g2, 256, SMEM2>>>();

    int n4 = out_size / 4;
    k_sum<<<(n4 + 255) / 256, 256>>>((float4*)out, n4);
}

// round 17
// speedup vs baseline: 1.0297x; 1.0297x over previous
#include <cuda_runtime.h>
#include <cuda_fp16.h>
#include <math.h>
#include <stdint.h>

// Problem constants
#define NE 12
#define NT 4096
#define NH 2048
#define NF 1280

// Shared GEMM geometry: K-chunk 64, SMEM rows 64 fp16 + 8 pad = 144B
#define CH 64
#define ROWB 144
#define APL (64 * ROWB)               // 9216  B: 64-row plane
#define BPL (128 * ROWB)              // 18432 B: 128-row plane
// ffn1: CTA 64x128, warps 2x4 (tile 32x32)
#define STG1 (APL + 2 * BPL)          // 46080: A(64), B1(128), B3(128)
#define SMEM1 (1024 + 2 * STG1)       // 93184 -> 2 CTAs/SM, 2-stage
// ffn2: CTA 128x128, warps 4x2 (tile 32x64)
#define STG2 (2 * BPL)                // 36864: A(128), B(128)
#define SMEM2 (2 * STG2)              // 73728 -> 2 CTAs/SM, 2-stage

// Scratch (static __device__ globals — allocation-free per harness rules)
// g_cnt is zero at module load; block 0 of k_sum (last kernel in the graph)
// re-zeroes it so every graph replay's k_prep starts from a clean state.
__device__ int     g_cnt[NE];
__device__ int     g_tok[NE * NT];
__device__ uint8_t g_which[NE * NT];
__device__ float   g_wgt[NE * NT];
__device__ __align__(16) uint16_t g_w1f[(size_t)NE * NF * NH];   // fp16 weights
__device__ __align__(16) uint16_t g_w3f[(size_t)NE * NF * NH];
__device__ __align__(16) uint16_t g_w2f[(size_t)NE * NH * NF];
__device__ __align__(16) uint16_t g_xf[(size_t)NT * NH];         // fp16 x
__device__ __align__(16) uint16_t g_hf[(size_t)NE * NT * NF];    // fp16 h
__device__ __align__(16) float    g_part[2][(size_t)NT * NH];    // per-choice partials

// ---------------------------------------------------------------------------
// helpers
// ---------------------------------------------------------------------------
__device__ __forceinline__ uint32_t s2u(const void* p) {
    uint32_t a;
    asm("{ .reg .u64 t; cvta.to.shared.u64 t, %1; cvt.u32.u64 %0, t; }"
        : "=r"(a) : "l"(p));
    return a;
}

__device__ __forceinline__ void ldm4(uint32_t r[4], uint32_t a) {
    asm volatile("ldmatrix.sync.aligned.m8n8.x4.shared.b16 {%0,%1,%2,%3}, [%4];"
                 : "=r"(r[0]), "=r"(r[1]), "=r"(r[2]), "=r"(r[3]) : "r"(a));
}

__device__ __forceinline__ void mmaf16(float c[4], const uint32_t a[4],
                                       uint32_t b0, uint32_t b1) {
    asm volatile(
        "mma.sync.aligned.m16n8k16.row.col.f32.f16.f16.f32 "
        "{%0,%1,%2,%3},{%4,%5,%6,%7},{%8,%9},{%0,%1,%2,%3};"
        : "+f"(c[0]), "+f"(c[1]), "+f"(c[2]), "+f"(c[3])
        : "r"(a[0]), "r"(a[1]), "r"(a[2]), "r"(a[3]), "r"(b0), "r"(b1));
}

__device__ __forceinline__ void cpa16(uint32_t dst, const void* src) {
    asm volatile("cp.async.cg.shared.global [%0], [%1], 16;" :: "r"(dst), "l"(src));
}
#define CP_COMMIT() asm volatile("cp.async.commit_group;" ::: "memory")
#define CP_WAIT(n)  asm volatile("cp.async.wait_group %0;" :: "n"(n) : "memory")

// ---------------------------------------------------------------------------
// k_prep (route + w1/w3 split; w2 split lives in ffn1's grid tail) / k_sum
// ---------------------------------------------------------------------------
#define NW4 (NE * NF * NH / 4)         // 7,864,320 float4s per weight tensor
#define ROUTE_BLOCKS (NT / 8)          // 512 blocks x 8 warps = 1 warp/token
#define PREP_SPLIT_BLOCKS ((2 * NW4 + 255) / 256)

__global__ void k_prep(const float4* __restrict__ w1,
                       const float4* __restrict__ w3,
                       const float*  __restrict__ x,
                       const float*  __restrict__ gw) {
    if (blockIdx.x < ROUTE_BLOCKS) {
        int wid = threadIdx.x >> 5, lane = threadIdx.x & 31;
        int tok = blockIdx.x * 8 + wid;
        const float* xr = x + (size_t)tok * NH;
        uint16_t* xo = g_xf + (size_t)tok * NH;
        float acc[NE];
#pragma unroll
        for (int e = 0; e < NE; e++) acc[e] = 0.f;
        for (int i = lane; i < NH; i += 32) {
            float xv = xr[i];
            __half hv = __float2half_rn(xv);
            xo[i] = *(uint16_t*)&hv;
#pragma unroll
            for (int e = 0; e < NE; e++) acc[e] = fmaf(xv, gw[e * NH + i], acc[e]);
        }
#pragma unroll
        for (int e = 0; e < NE; e++) {
#pragma unroll
            for (int o = 16; o > 0; o >>= 1)
                acc[e] += __shfl_xor_sync(0xffffffffu, acc[e], o);
        }
        if (lane == 0) {
            int i1 = 0;
#pragma unroll
            for (int e = 1; e < NE; e++) if (acc[e] > acc[i1]) i1 = e;
            int i2 = (i1 == 0) ? 1 : 0;
#pragma unroll
            for (int e = 0; e < NE; e++) if (e != i1 && acc[e] > acc[i2]) i2 = e;
            float wA = 1.f / (1.f + expf(acc[i2] - acc[i1]));
            float wB = 1.f - wA;
            int p1 = atomicAdd(&g_cnt[i1], 1);
            g_tok[i1 * NT + p1] = tok; g_wgt[i1 * NT + p1] = wA; g_which[i1 * NT + p1] = 0;
            int p2 = atomicAdd(&g_cnt[i2], 1);
            g_tok[i2 * NT + p2] = tok; g_wgt[i2 * NT + p2] = wB; g_which[i2 * NT + p2] = 1;
        }
        return;
    }
    long long i = (long long)(blockIdx.x - ROUTE_BLOCKS) * blockDim.x + threadIdx.x;
    const float4* s; uint2* d; long long j;
    if (i < NW4)            { s = w1; d = (uint2*)g_w1f; j = i; }
    else if (i < 2LL * NW4) { s = w3; d = (uint2*)g_w3f; j = i - NW4; }
    else return;
    float4 v = s[j];
    __half2 a = __floats2half2_rn(v.x, v.y);
    __half2 b = __floats2half2_rn(v.z, v.w);
    uint2 o; o.x = *(uint32_t*)&a; o.y = *(uint32_t*)&b;
    d[j] = o;
}

// out = part0 + part1; block 0 also resets g_cnt for the next graph replay.
__global__ void k_sum(float4* __restrict__ out, int n4) {
    int i = blockIdx.x * blockDim.x + threadIdx.x;
    if (blockIdx.x == 0 && threadIdx.x < NE) g_cnt[threadIdx.x] = 0;
    if (i < n4) {
        float4 a = ((const float4*)g_part[0])[i];
        float4 b = ((const float4*)g_part[1])[i];
        out[i] = make_float4(a.x + b.x, a.y + b.y, a.z + b.z, a.w + b.w);
    }
}

// ---------------------------------------------------------------------------
// k_ffn1: fused x@w1^T, x@w3^T (fp16) + SwiGLU -> fp16 h.  (R13/R15 GEMM body)
// Grid z in [0, NE): GEMM. Grid z in [NE, NE+W2Z): w2 fp32->fp16 split —
// those 2560 blocks are scheduled LAST (z outermost) and fill the idle SM
// slots left by early-exiting m-tiles, overlapping the split with compute.
// ffn2 (same stream) starts only after all ffn1 blocks finish.
// ---------------------------------------------------------------------------
#define W2Z 4
#define W2_BLOCKS (W2Z * (NT / 64) * (NF / 128))    // 2560
#define W2_ITERS  (NW4 / (W2_BLOCKS * 256))         // 12 (exact)

__global__ __launch_bounds__(256, 2) void k_ffn1(const float4* __restrict__ w2) {
    if (blockIdx.z >= NE) {
        // w2 split tail: 12 float4s per thread, grid-strided (coalesced)
        long long b = ((long long)(blockIdx.z - NE) * gridDim.y + blockIdx.y)
                      * gridDim.x + blockIdx.x;
        long long i = b * 256 + threadIdx.x;
        uint2* d = (uint2*)g_w2f;
#pragma unroll
        for (int k = 0; k < W2_ITERS; k++) {
            float4 v = w2[i];
            __half2 a = __floats2half2_rn(v.x, v.y);
            __half2 bb = __floats2half2_rn(v.z, v.w);
            uint2 o; o.x = *(uint32_t*)&a; o.y = *(uint32_t*)&bb;
            d[i] = o;
            i += (long long)W2_BLOCKS * 256;
        }
        return;
    }

    int e = blockIdx.z;
    int cnt = g_cnt[e];
    int m0 = blockIdx.y * 64;
    if (m0 >= cnt) return;
    int n0 = blockIdx.x * 128;

    extern __shared__ char sm[];
    int* stok = (int*)sm;
    uint32_t su = s2u(sm);
    int tid = threadIdx.x, lane = tid & 31, wid = tid >> 5;
    int wM = wid >> 2, wN = wid & 3;

    if (tid < 64) {
        int r = m0 + tid;
        if (r >= cnt) r = cnt - 1;
        stok[tid] = g_tok[e * NT + r];
    }
    __syncthreads();

    const size_t wb = ((size_t)e * NF + n0) * NH;

    int ach = tid & 7, ar0 = tid >> 3;
    int bpl = tid & 1, bch = (tid >> 1) & 7, br0 = tid >> 4;
    const uint16_t* bsrc = (bpl ? g_w3f : g_w1f);
    const uint16_t* apt0 = g_xf + (size_t)stok[ar0] * NH + ach * 8;
    const uint16_t* apt1 = g_xf + (size_t)stok[ar0 + 32] * NH + ach * 8;
    const uint16_t* bpt  = bsrc + wb + (size_t)br0 * NH + bch * 8;
    uint32_t adst0 = (uint32_t)(ar0 * ROWB + ach * 16);
    uint32_t bdst0 = (uint32_t)(APL + bpl * BPL + br0 * ROWB + bch * 16);

    float C1[2][4][4], C3[2][4][4];
#pragma unroll
    for (int i = 0; i < 2; i++)
#pragma unroll
        for (int j = 0; j < 4; j++)
#pragma unroll
            for (int q = 0; q < 4; q++) { C1[i][j][q] = 0.f; C3[i][j][q] = 0.f; }

    auto issue = [&](int c, uint32_t sb) {
        int k0 = c * CH;
        cpa16(sb + adst0,             apt0 + k0);
        cpa16(sb + adst0 + 32 * ROWB, apt1 + k0);
#pragma unroll
        for (int j = 0; j < 8; j++)
            cpa16(sb + bdst0 + 16 * j * ROWB, bpt + k0 + (size_t)(16 * j) * NH);
        CP_COMMIT();
    };

    auto compute = [&](uint32_t sb) {
#pragma unroll
        for (int kk = 0; kk < 4; kk++) {
            uint32_t ao = sb + (wM * 32 + (lane & 15)) * ROWB + (lane >> 4) * 16 + kk * 32;
            uint32_t bo = sb + APL + (wN * 32 + (lane & 15)) * ROWB + (lane >> 4) * 16 + kk * 32;
            uint32_t ah[2][4], b1[2][4], b3[2][4];
#pragma unroll
            for (int mf = 0; mf < 2; mf++)
                ldm4(ah[mf], ao + mf * 16 * ROWB);
#pragma unroll
            for (int g = 0; g < 2; g++) {
                ldm4(b1[g], bo + g * 16 * ROWB);
                ldm4(b3[g], bo + BPL + g * 16 * ROWB);
            }
#pragma unroll
            for (int mf = 0; mf < 2; mf++)
#pragma unroll
                for (int nf = 0; nf < 4; nf++) {
                    int g = nf >> 1, o = nf & 1;
                    mmaf16(C1[mf][nf], ah[mf], b1[g][o], b1[g][o + 2]);
                }
#pragma unroll
            for (int mf = 0; mf < 2; mf++)
#pragma unroll
                for (int nf = 0; nf < 4; nf++) {
                    int g = nf >> 1, o = nf & 1;
                    mmaf16(C3[mf][nf], ah[mf], b3[g][o], b3[g][o + 2]);
                }
        }
    };

    constexpr int NC = NH / CH;   // 32 (even)
    issue(0, su + 1024);

#pragma unroll 1
    for (int c = 0; c < NC; c += 2) {
        CP_WAIT(0);
        __syncthreads();
        if (c + 1 < NC) issue(c + 1, su + 1024 + STG1);
        compute(su + 1024);
        CP_WAIT(0);
        __syncthreads();
        if (c + 2 < NC) issue(c + 2, su + 1024);
        compute(su + 1024 + STG1);
    }

    // Epilogue: h = silu(c1)*c3*wgt -> fp16
#pragma unroll
    for (int mf = 0; mf < 2; mf++)
#pragma unroll
        for (int nf = 0; nf < 4; nf++) {
            int rb = m0 + wM * 32 + mf * 16 + (lane >> 2);
            int cc = n0 + wN * 32 + nf * 8 + (lane & 3) * 2;
#pragma unroll
            for (int hf = 0; hf < 2; hf++) {
                int r = rb + hf * 8;
                if (r < cnt) {
                    float wg = g_wgt[e * NT + r];
                    float a0 = C1[mf][nf][hf * 2], a1 = C1[mf][nf][hf * 2 + 1];
                    float h0 = a0 / (1.f + expf(-a0)) * C3[mf][nf][hf * 2] * wg;
                    float h1 = a1 / (1.f + expf(-a1)) * C3[mf][nf][hf * 2 + 1] * wg;
                    size_t off = (size_t)(e * NT + r) * NF + cc;
                    __half2 hv = __floats2half2_rn(h0, h1);
                    *(uint32_t*)(g_hf + off) = *(uint32_t*)&hv;
                }
            }
        }
}

// ---------------------------------------------------------------------------
// k_ffn2: partial[which][tok] = h @ w2^T slice.  (R13/R15 exact)
// CTA 128x128, 8 warps 4Mx2N (warp tile 32x64). 2-stage, 2 CTAs/SM.
// ---------------------------------------------------------------------------
__global__ __launch_bounds__(256, 2) void k_ffn2() {
    int e = blockIdx.z;
    int cnt = g_cnt[e];
    int m0 = blockIdx.y * 128;
    if (m0 >= cnt) return;
    int n0 = blockIdx.x * 128;

    extern __shared__ char sm[];
    uint32_t su = s2u(sm);
    int tid = threadIdx.x, lane = tid & 31, wid = tid >> 5;
    int wM = wid >> 1, wN = wid & 1;

    const size_t wb = ((size_t)e * NH + n0) * NF;
    const size_t hb = (size_t)e * NT * NF;

    int ach = tid & 7, ar0 = tid >> 3;                  // A rows ar0+32j, j<4
    int bch = tid & 7, br0 = tid >> 3;                  // B rows br0+32j, j<4
    const uint16_t* apt[4];
#pragma unroll
    for (int j = 0; j < 4; j++) {
        int r = m0 + ar0 + 32 * j;
        if (r >= cnt) r = cnt - 1;
        apt[j] = g_hf + hb + (size_t)r * NF + ach * 8;
    }
    const uint16_t* bpt = g_w2f + wb + (size_t)br0 * NF + bch * 8;
    uint32_t adst0 = (uint32_t)(ar0 * ROWB + ach * 16);
    uint32_t bdst0 = (uint32_t)(BPL + br0 * ROWB + bch * 16);

    float C[2][8][4];
#pragma unroll
    for (int i = 0; i < 2; i++)
#pragma unroll
        for (int j = 0; j < 8; j++)
#pragma unroll
            for (int q = 0; q < 4; q++) C[i][j][q] = 0.f;

    auto issue = [&](int c, uint32_t sb) {
        int k0 = c * CH;
#pragma unroll
        for (int j = 0; j < 4; j++)
            cpa16(sb + adst0 + 32 * j * ROWB, apt[j] + k0);
#pragma unroll
        for (int j = 0; j < 4; j++)
            cpa16(sb + bdst0 + 32 * j * ROWB, bpt + k0 + (size_t)(32 * j) * NF);
        CP_COMMIT();
    };

    auto compute = [&](uint32_t sb) {
#pragma unroll
        for (int kk = 0; kk < 4; kk++) {
            uint32_t ao = sb + (wM * 32 + (lane & 15)) * ROWB + (lane >> 4) * 16 + kk * 32;
            uint32_t bo = sb + BPL + (wN * 64 + (lane & 15)) * ROWB + (lane >> 4) * 16 + kk * 32;
            uint32_t ah[2][4], b[4][4];
#pragma unroll
            for (int mf = 0; mf < 2; mf++)
                ldm4(ah[mf], ao + mf * 16 * ROWB);
#pragma unroll
            for (int g = 0; g < 4; g++)
                ldm4(b[g], bo + g * 16 * ROWB);
#pragma unroll
            for (int mf = 0; mf < 2; mf++)
#pragma unroll
                for (int nf = 0; nf < 8; nf++) {
                    int g = nf >> 1, o = nf & 1;
                    mmaf16(C[mf][nf], ah[mf], b[g][o], b[g][o + 2]);
                }
        }
    };

    constexpr int NC = NF / CH;   // 20 (even)
    issue(0, su);

#pragma unroll 1
    for (int c = 0; c < NC; c += 2) {
        CP_WAIT(0);
        __syncthreads();
        if (c + 1 < NC) issue(c + 1, su + STG2);
        compute(su);
        CP_WAIT(0);
        __syncthreads();
        if (c + 2 < NC) issue(c + 2, su);
        compute(su + STG2);
    }

    // Epilogue: direct store to partial plane (each (tok,which) written once)
#pragma unroll
    for (int mf = 0; mf < 2; mf++)
#pragma unroll
        for (int nf = 0; nf < 8; nf++) {
            int rb = m0 + wM * 32 + mf * 16 + (lane >> 2);
            int cc = n0 + wN * 64 + nf * 8 + (lane & 3) * 2;
#pragma unroll
            for (int hf = 0; hf < 2; hf++) {
                int r = rb + hf * 8;
                if (r < cnt) {
                    int tok = g_tok[e * NT + r];
                    int wh  = g_which[e * NT + r];
                    float* p = g_part[wh] + (size_t)tok * NH + cc;
                    p[0] = C[mf][nf][hf * 2 + 0];
                    p[1] = C[mf][nf][hf * 2 + 1];
                }
            }
        }
}

// ---------------------------------------------------------------------------
// kernel_launch: prep (route + w1/w3) -> ffn1 (+w2 split tail) -> ffn2 -> sum
// ---------------------------------------------------------------------------
extern "C" void kernel_launch(void* const* d_in, const int* in_sizes, int n_in,
                              void* d_out, int out_size) {
    const float* x  = (const float*)d_in[0];
    const float* gw = (const float*)d_in[1];
    const float* w1 = (const float*)d_in[2];
    const float* w2 = (const float*)d_in[3];
    const float* w3 = (const float*)d_in[4];
    float* out = (float*)d_out;
    (void)in_sizes; (void)n_in;

    static bool attr_set = false;
    if (!attr_set) {
        cudaFuncSetAttribute(k_ffn1, cudaFuncAttributeMaxDynamicSharedMemorySize, SMEM1);
        cudaFuncSetAttribute(k_ffn2, cudaFuncAttributeMaxDynamicSharedMemorySize, SMEM2);
        attr_set = true;
    }

    k_prep<<<ROUTE_BLOCKS + PREP_SPLIT_BLOCKS, 256>>>(
        (const float4*)w1, (const float4*)w3, x, gw);

    dim3 g1(NF / 128, NT / 64, NE + W2Z);   // (10, 64, 16): z>=12 = w2 split
    k_ffn1<<<g1, 256, SMEM1>>>((const float4*)w2);

    dim3 g2(NH / 128, NT / 128, NE);        // (16, 32, 12)
    k_ffn2<<<g2, 256, SMEM2>>>();

    int n4 = out_size / 4;
    k_sum<<<(n4 + 255) / 256, 256>>>((float4*)out, n4);
}